// round 7
// baseline (speedup 1.0000x reference)
#include <cuda_runtime.h>
#include <cstddef>

// Problem constants (fixed by the dataset)
#define BS    32
#define NFEAT 64
#define NN    512      // N (graph nodes / m dim)
#define JJ    4
#define NOUT  128
#define CDIM  (JJ * NFEAT)        // 256 channels
#define ROWF4 512                 // one W n-row = 2048 floats = 512 float4
#define NCHUNK 16                 // chunk-blocks per batch
#define NPERCHUNK (NN / NCHUNK)   // 32 n-rows per block

// Per-(b,chunk) partial sums of W over n. 32*16*2048 floats = 4 MB, L2-hot.
__device__ float g_Spart[BS * NCHUNK * 2048];
// Per-batch completion counters. atomicInc with wrap=NCHUNK-1 self-resets to 0
// after exactly NCHUNK increments -> deterministic across graph replays.
__device__ unsigned int g_cnt[BS];

// ---------------------------------------------------------------------------
// Single fused kernel.
// Stream phase (all 512 blocks): Spart[b,chunk,:] = sum of 32 n-rows of W.
//   512 threads x float4 = one whole 8KB n-row per iteration, coalesced,
//   __ldcs evict-first (W read exactly once, exceeds L2). Proven 74%-DRAM shape.
// Epilogue phase (last block per batch, overlapped with other batches' stream):
//   Ssh[j][m] = sum_c Spart[b][c][m*4+j]        (128 KB L2-hot)
//   Gsh[j*64+f] = sum_m Ssh[j][m] * X[b][f][m]  (L2-hot X)
//   y[b][o] = fc_w[o,:] . Gsh + 512*fc_b[o]
// ---------------------------------------------------------------------------
__global__ __launch_bounds__(512) void fused_kernel(
    const float4* __restrict__ W4,
    const float* __restrict__ X,
    const float* __restrict__ fc_w,
    const float* __restrict__ fc_b,
    float* __restrict__ out)
{
    __shared__ float Ssh[JJ][NN];   // 8 KB
    __shared__ float Gsh[CDIM];     // 1 KB
    __shared__ int isLast;

    const int chunk = blockIdx.x;   // fast dim: batch b's 16 blocks are adjacent
    const int b     = blockIdx.y;
    const int t     = threadIdx.x;  // 0..511

    // ---- stream phase ----
    {
        const size_t row0 = ((size_t)b * NN + (size_t)chunk * NPERCHUNK) * ROWF4;
        const float4* __restrict__ base = W4 + row0;

        float4 acc = make_float4(0.f, 0.f, 0.f, 0.f);
#pragma unroll
        for (int i = 0; i < NPERCHUNK; ++i) {
            float4 v = __ldcs(&base[(size_t)i * ROWF4 + t]);
            acc.x += v.x; acc.y += v.y; acc.z += v.z; acc.w += v.w;
        }
        float4* out4 = reinterpret_cast<float4*>(g_Spart);
        out4[((size_t)b * NCHUNK + chunk) * ROWF4 + t] = acc;  // default caching: L2-hot
    }

    // ---- completion detection (threadFenceReduction pattern) ----
    __threadfence();
    if (t == 0) {
        unsigned old = atomicInc(&g_cnt[b], NCHUNK - 1);  // wraps to 0 -> self-reset
        isLast = (old == NCHUNK - 1);
    }
    __syncthreads();
    if (!isLast) return;

    // ================= epilogue for batch b (one block, 512 thr) =============
    const int w    = t >> 5;        // warp 0..15
    const int lane = t & 31;

    // phase 1: reduce 16 chunk partials -> Ssh[j][m] (coalesced, L2-hot)
    const float* __restrict__ part = g_Spart + (size_t)b * NCHUNK * 2048;
#pragma unroll
    for (int i = 0; i < 4; ++i) {
        const int slot = t + i * 512;            // 0..2047 = m*4+j
        float a = 0.f;
#pragma unroll
        for (int c = 0; c < NCHUNK; ++c) a += part[(size_t)c * 2048 + slot];
        Ssh[slot & 3][slot >> 2] = a;
    }
    __syncthreads();

    // phase 2: G. Each warp handles 4 f's; lanes stride m (coalesced X, L2-hot).
    const float* __restrict__ Xb = X + (size_t)b * NFEAT * NN;
#pragma unroll
    for (int fi = 0; fi < 4; ++fi) {
        const int f = w * 4 + fi;                // 0..63
        float a0 = 0.f, a1 = 0.f, a2 = 0.f, a3 = 0.f;
#pragma unroll
        for (int i = 0; i < 16; ++i) {
            const int m = i * 32 + lane;
            const float xv = Xb[(size_t)f * NN + m];
            a0 += Ssh[0][m] * xv;
            a1 += Ssh[1][m] * xv;
            a2 += Ssh[2][m] * xv;
            a3 += Ssh[3][m] * xv;
        }
#pragma unroll
        for (int s = 16; s > 0; s >>= 1) {
            a0 += __shfl_xor_sync(0xffffffffu, a0, s);
            a1 += __shfl_xor_sync(0xffffffffu, a1, s);
            a2 += __shfl_xor_sync(0xffffffffu, a2, s);
            a3 += __shfl_xor_sync(0xffffffffu, a3, s);
        }
        if (lane == 0) {
            Gsh[0 * NFEAT + f] = a0;
            Gsh[1 * NFEAT + f] = a1;
            Gsh[2 * NFEAT + f] = a2;
            Gsh[3 * NFEAT + f] = a3;
        }
    }
    __syncthreads();

    // phase 3: y. Each warp handles 8 o's; lanes stride c (coalesced fc_w).
#pragma unroll
    for (int oi = 0; oi < 8; ++oi) {
        const int o = w * 8 + oi;                // 0..127
        const float* __restrict__ wrow = fc_w + (size_t)o * CDIM;
        float a = 0.f;
#pragma unroll
        for (int i = 0; i < 8; ++i) {
            const int c = i * 32 + lane;
            a += wrow[c] * Gsh[c];
        }
#pragma unroll
        for (int s = 16; s > 0; s >>= 1) a += __shfl_xor_sync(0xffffffffu, a, s);
        if (lane == 0) out[(size_t)b * NOUT + o] = a + (float)NN * fc_b[o];
    }
}

// ---------------------------------------------------------------------------
// Inputs (metadata order): X[32,64,512] f32, W[32,512,512,4] f32,
// fc_w[128,256] f32, fc_b[128] f32, N_batch (int), mask[32,512] f32 (unused).
// Output: y[32,128] f32.
// ---------------------------------------------------------------------------
extern "C" void kernel_launch(void* const* d_in, const int* in_sizes, int n_in,
                              void* d_out, int out_size)
{
    const float* X    = (const float*)d_in[0];
    const float* W    = (const float*)d_in[1];
    const float* fc_w = (const float*)d_in[2];
    const float* fc_b = (const float*)d_in[3];
    float*       out  = (float*)d_out;

    dim3 grid(NCHUNK, BS);   // chunk fast, batch slow -> early batches finish early
    fused_kernel<<<grid, 512>>>(reinterpret_cast<const float4*>(W),
                                X, fc_w, fc_b, out);
}